// round 6
// baseline (speedup 1.0000x reference)
#include <cuda_runtime.h>
#include <math.h>

// ---------------------------------------------------------------------------
// SpectralCoherence: out[a,y,z] = Re(I)/|F1|
// Exploits exact evenness of Phi11 in k2 -> fold k2 grid to 101 points and the
// sin(k2*dy) branch vanishes:
//   G[a,i,z]  = sum_j Phi[a,i,j] * w3[j]*cos(k3[j]*dz[z])
//   out[a,y,z]= sum_i (c_i*w2[i]*cos(k2[i]*dy[y])) * G[a,i,z] / |F1[a]|
// ---------------------------------------------------------------------------

#define NJ     201   // full k3 grid
#define NI     101   // folded k2 grid (upper half incl. 0)
#define NIP    112   // padded i rows (16*7)
#define NJP    224   // padded j (7 chunks of 32)
#define NZ     64
#define NY     64
#define CHUNK  32
#define NCHUNK 7
#define SPHI_LD 33   // smem Phi row stride
#define SG_LD   68   // smem G row stride (multiple of 4 for float4)

__device__ float g_kg[NJ];                      // full symmetric grid
__device__ float g_w[NJ];                       // trapz weights
__device__ float g_k2u[NI];                     // upper-half k2 values
__device__ float g_Wi[NIP];                     // fold*w2, zero-padded
__device__ __align__(16) float g_CZ[NJP * NZ];  // w3[j]*cos(k3[j]*dz[z]), zero-padded rows
__device__ __align__(16) float g_CY[NIP * NY];  // Wi[i]*cos(k2u[i]*dy[y]), zero-padded rows

// ---------------------------------------------------------------------------
__global__ void setup_kernel(const float* __restrict__ dy,
                             const float* __restrict__ dz) {
    const int tid = threadIdx.x;

    // grid: concat(-gp[::-1], 0, gp), gp = (10^linspace(-2,2,100))^2
    for (int t = tid; t < NJ; t += blockDim.x) {
        double v;
        if (t == 100) {
            v = 0.0;
        } else if (t > 100) {
            int m = t - 101;
            v = pow(10.0, -4.0 + 8.0 * (double)m / 99.0);
        } else {
            int m = 99 - t;
            v = -pow(10.0, -4.0 + 8.0 * (double)m / 99.0);
        }
        g_kg[t] = (float)v;
    }
    __syncthreads();

    // trapz weights
    for (int t = tid; t < NJ; t += blockDim.x) {
        float wl = (t == 0)      ? 0.0f : 0.5f * (g_kg[t] - g_kg[t - 1]);
        float wr = (t == NJ - 1) ? 0.0f : 0.5f * (g_kg[t + 1] - g_kg[t]);
        g_w[t] = wl + wr;
    }
    __syncthreads();

    // folded k2 + fold weights
    for (int t = tid; t < NIP; t += blockDim.x) {
        if (t < NI) {
            g_k2u[t] = g_kg[100 + t];
            g_Wi[t]  = (t == 0) ? g_w[100] : 2.0f * g_w[100 + t];
        } else {
            g_Wi[t] = 0.0f;
        }
    }
    __syncthreads();

    // CZ[j,z] = w3[j] * cos(k3[j]*dz[z])   (zero for padded j)
    for (int t = tid; t < NJP * NZ; t += blockDim.x) {
        int j = t >> 6, z = t & 63;
        float v = 0.0f;
        if (j < NJ) v = g_w[j] * cosf(g_kg[j] * dz[z]);
        g_CZ[t] = v;
    }
    // CY[i,y] = Wi[i] * cos(k2u[i]*dy[y])  (zero for padded i)
    for (int t = tid; t < NIP * NY; t += blockDim.x) {
        int i = t >> 6, y = t & 63;
        float v = 0.0f;
        if (i < NI) v = g_Wi[i] * cosf(g_k2u[i] * dy[y]);
        g_CY[t] = v;
    }
}

// ---------------------------------------------------------------------------
__global__ void __launch_bounds__(256, 3)
spectral_kernel(const float* __restrict__ k1p,
                const float* __restrict__ pLogL,
                const float* __restrict__ pLogT,
                const float* __restrict__ pLogM,
                float* __restrict__ out) {
    extern __shared__ float smem[];
    float* sPhi = smem;                    // NIP * SPHI_LD
    float* sG   = smem + NIP * SPHI_LD;    // NIP * SG_LD
    __shared__ float sRed[8];
    __shared__ float sInvDen;

    const int tid = threadIdx.x;
    const int a   = blockIdx.x;

    const float k1   = __ldg(&k1p[a]);
    const float L    = expf(__ldg(pLogL));
    const float T    = expf(__ldg(pLogT));
    const float M    = expf(__ldg(pLogM));
    const float L2   = L * L;
    const float M4pi = M * 0.079577471545947667884f;  // M/(4*pi)
    const float k1sq = k1 * k1;

    // phase A mapping: fixed column jl per thread, rows i0+8k
    const int jl = tid & 31;
    const int i0 = tid >> 5;
    // phase B mapping: 16x16, rows 7*ti..7*ti+6, z = 4*tz..4*tz+3
    const int tz = tid & 15;
    const int ti = tid >> 4;

    float acc[7][4];
#pragma unroll
    for (int r = 0; r < 7; ++r)
#pragma unroll
        for (int c = 0; c < 4; ++c) acc[r][c] = 0.0f;

    float f1 = 0.0f;

    for (int ch = 0; ch < NCHUNK; ++ch) {
        const int jbase = ch * CHUNK;
        const int j = jbase + jl;
        const bool jvalid = (j < NJ);
        const float k3v = jvalid ? __ldg(&g_kg[j]) : 0.0f;
        const float w3v = jvalid ? __ldg(&g_w[j]) : 0.0f;
        const float k3sq = k3v * k3v;

        // --- Phase A: compute Phi chunk into smem ---
#pragma unroll 1
        for (int k = 0; k < 14; ++k) {
            const int i = i0 + 8 * k;  // 0..111
            float phi = 0.0f;
            if (i < NI && jvalid) {
                const float k2 = __ldg(&g_k2u[i]);
                const float s  = k1sq + k2 * k2;
                const float kk = s + k3sq;
                const float beta = T * exp2f(-(1.0f / 3.0f) * __log2f(L2 * kk));
                const float k30  = k3v + beta * k1;
                const float kk0  = s + k30 * k30;
                const float q    = L2 * kk0;
                const float e0   = M4pi * exp2f(2.0f * __log2f(q)
                                                - (17.0f / 6.0f) * __log2f(1.0f + q));
                const float C1 = beta * k1sq
                                 * (kk0 - 2.0f * k30 * k30 + beta * k1 * k30)
                                 * __fdividef(1.0f, kk * s);
                const float rs = sqrtf(s);
                const float at = atan2f(beta * k1 * rs, kk0 - k30 * k1 * beta);
                const float C2 = k2 * kk0 * __fdividef(1.0f, s * rs) * at;
                const float zeta = C1 - __fdividef(k2, k1) * C2;
                const float ik0  = __fdividef(1.0f, kk0);
                phi = e0 * ik0 * ik0
                      * (kk0 - k1sq - 2.0f * k1 * k30 * zeta + s * zeta * zeta);
                f1 += phi * (__ldg(&g_Wi[i]) * w3v);
            }
            sPhi[i * SPHI_LD + jl] = phi;
        }
        __syncthreads();

        // --- Phase B: G += Phi_chunk * CZ_chunk ---
#pragma unroll 4
        for (int jl2 = 0; jl2 < CHUNK; ++jl2) {
            const int jg = jbase + jl2;  // < NJP, CZ zero-padded
            const float4 cz = *reinterpret_cast<const float4*>(&g_CZ[jg * NZ + 4 * tz]);
#pragma unroll
            for (int r = 0; r < 7; ++r) {
                const float ph = sPhi[(7 * ti + r) * SPHI_LD + jl2];
                acc[r][0] += ph * cz.x;
                acc[r][1] += ph * cz.y;
                acc[r][2] += ph * cz.z;
                acc[r][3] += ph * cz.w;
            }
        }
        __syncthreads();
    }

    // dump G to smem
#pragma unroll
    for (int r = 0; r < 7; ++r) {
        const int i = 7 * ti + r;
        float4 v;
        v.x = acc[r][0]; v.y = acc[r][1]; v.z = acc[r][2]; v.w = acc[r][3];
        *reinterpret_cast<float4*>(&sG[i * SG_LD + 4 * tz]) = v;
    }

    // reduce F1 -> 1/|F1|
#pragma unroll
    for (int off = 16; off > 0; off >>= 1)
        f1 += __shfl_down_sync(0xffffffffu, f1, off);
    if ((tid & 31) == 0) sRed[tid >> 5] = f1;
    __syncthreads();
    if (tid == 0) {
        float s = 0.0f;
#pragma unroll
        for (int u = 0; u < 8; ++u) s += sRed[u];
        sInvDen = __fdividef(1.0f, fabsf(s));
    }
    __syncthreads();

    // --- Phase C: out[y,z] = (sum_i CY[i,y]*G[i,z]) * invDen ---
    const int tz2 = tid & 15;
    const int ty2 = tid >> 4;
    float o[4][4];
#pragma unroll
    for (int cy = 0; cy < 4; ++cy)
#pragma unroll
        for (int cz = 0; cz < 4; ++cz) o[cy][cz] = 0.0f;

#pragma unroll 4
    for (int i = 0; i < NIP; ++i) {
        const float4 cy = *reinterpret_cast<const float4*>(&g_CY[i * NY + 4 * ty2]);
        const float4 g  = *reinterpret_cast<const float4*>(&sG[i * SG_LD + 4 * tz2]);
        o[0][0] += cy.x * g.x; o[0][1] += cy.x * g.y; o[0][2] += cy.x * g.z; o[0][3] += cy.x * g.w;
        o[1][0] += cy.y * g.x; o[1][1] += cy.y * g.y; o[1][2] += cy.y * g.z; o[1][3] += cy.y * g.w;
        o[2][0] += cy.z * g.x; o[2][1] += cy.z * g.y; o[2][2] += cy.z * g.z; o[2][3] += cy.z * g.w;
        o[3][0] += cy.w * g.x; o[3][1] += cy.w * g.y; o[3][2] += cy.w * g.z; o[3][3] += cy.w * g.w;
    }

    const float inv = sInvDen;
    float* outa = out + (size_t)a * (NY * NZ);
#pragma unroll
    for (int cy = 0; cy < 4; ++cy) {
        const int y = 4 * ty2 + cy;
        float4 v;
        v.x = o[cy][0] * inv;
        v.y = o[cy][1] * inv;
        v.z = o[cy][2] * inv;
        v.w = o[cy][3] * inv;
        *reinterpret_cast<float4*>(&outa[y * NZ + 4 * tz2]) = v;
    }
}

// ---------------------------------------------------------------------------
extern "C" void kernel_launch(void* const* d_in, const int* in_sizes, int n_in,
                              void* d_out, int out_size) {
    const float* k1 = (const float*)d_in[0];
    const float* dy = (const float*)d_in[1];
    const float* dz = (const float*)d_in[2];
    const float* lL = (const float*)d_in[3];
    const float* lT = (const float*)d_in[4];
    const float* lM = (const float*)d_in[5];

    const int na = in_sizes[0];

    setup_kernel<<<1, 256>>>(dy, dz);

    const size_t smem = (size_t)(NIP * SPHI_LD + NIP * SG_LD) * sizeof(float);
    spectral_kernel<<<na, 256, smem>>>(k1, lL, lT, lM, (float*)d_out);
}

// round 8
// speedup vs baseline: 1.2304x; 1.2304x over previous
#include <cuda_runtime.h>
#include <math.h>

// ---------------------------------------------------------------------------
// SpectralCoherence: out[a,y,z] = Re(I)/|F1|
// Phi11 is even in k2 -> fold k2 grid to 101 points; sin branch vanishes:
//   G[a,i,z]  = sum_j Phi[a,i,j] * w3[j]*cos(k3[j]*dz[z])
//   out[a,y,z]= sum_i (c_i*w2[i]*cos(k2[i]*dy[y])) * G[a,i,z] / |F1[a]|
// This round: fast-approx transcendentals, poly atan2, f32x2 packed FMA GEMMs.
// ---------------------------------------------------------------------------

#define NJ     201
#define NI     101
#define NIP    112
#define NJP    224
#define NZ     64
#define NY     64
#define CHUNK  32
#define NCHUNK 7
#define SPHI_LD 34   // even -> float2 LDS on pairs, rows 8B-aligned
#define SG_LD   68   // multiple of 4 -> float4/ulonglong2

typedef unsigned long long u64;

__device__ float g_kg[NJ];
__device__ float g_w[NJ];
__device__ float g_k2u[NI];
__device__ float g_Wi[NIP];
__device__ __align__(16) float g_CZ[NJP * NZ];
__device__ __align__(16) float g_CY[NIP * NY];

// ---- fast math helpers -----------------------------------------------------
__device__ __forceinline__ float fast_ex2(float x) {
    float r; asm("ex2.approx.f32 %0, %1;" : "=f"(r) : "f"(x)); return r;
}
__device__ __forceinline__ float fast_lg2(float x) {
    float r; asm("lg2.approx.f32 %0, %1;" : "=f"(r) : "f"(x)); return r;
}
__device__ __forceinline__ float fast_rcp(float x) {
    float r; asm("rcp.approx.f32 %0, %1;" : "=f"(r) : "f"(x)); return r;
}
__device__ __forceinline__ float fast_rsq(float x) {
    float r; asm("rsqrt.approx.f32 %0, %1;" : "=f"(r) : "f"(x)); return r;
}
// atan2(y, x) with y > 0 guaranteed. Minimax odd poly on [0,1], err ~1e-6 rad.
__device__ __forceinline__ float fast_atan2_pos(float y, float x) {
    const float ax = fabsf(x);
    const float mx = fmaxf(ax, y);
    const float mn = fminf(ax, y);
    const float t  = mn * fast_rcp(mx);
    const float t2 = t * t;
    float p = -0.0117212f;
    p = fmaf(p, t2,  0.05265332f);
    p = fmaf(p, t2, -0.11643287f);
    p = fmaf(p, t2,  0.19354346f);
    p = fmaf(p, t2, -0.33262347f);
    p = fmaf(p, t2,  0.99997726f);
    p = p * t;
    float r = (y > ax) ? (1.5707963267948966f - p) : p;
    if (x < 0.0f) r = 3.14159265358979323f - r;
    return r;
}
// ---- f32x2 packed FMA ------------------------------------------------------
__device__ __forceinline__ u64 pack2dup(float v) {
    u64 r; asm("mov.b64 %0, {%1, %1};" : "=l"(r) : "f"(v)); return r;
}
__device__ __forceinline__ void ffma2(u64& d, u64 a, u64 b) {
    asm("fma.rn.f32x2 %0, %1, %2, %3;" : "=l"(d) : "l"(a), "l"(b), "l"(d));
}
__device__ __forceinline__ float2 unpack2(u64 v) {
    float2 f; asm("mov.b64 {%0, %1}, %2;" : "=f"(f.x), "=f"(f.y) : "l"(v));
    return f;
}

// ---------------------------------------------------------------------------
__global__ void setup_kernel(const float* __restrict__ dy,
                             const float* __restrict__ dz) {
    const int tid = threadIdx.x;

    for (int t = tid; t < NJ; t += blockDim.x) {
        double v;
        if (t == 100) {
            v = 0.0;
        } else if (t > 100) {
            int m = t - 101;
            v = pow(10.0, -4.0 + 8.0 * (double)m / 99.0);
        } else {
            int m = 99 - t;
            v = -pow(10.0, -4.0 + 8.0 * (double)m / 99.0);
        }
        g_kg[t] = (float)v;
    }
    __syncthreads();

    for (int t = tid; t < NJ; t += blockDim.x) {
        float wl = (t == 0)      ? 0.0f : 0.5f * (g_kg[t] - g_kg[t - 1]);
        float wr = (t == NJ - 1) ? 0.0f : 0.5f * (g_kg[t + 1] - g_kg[t]);
        g_w[t] = wl + wr;
    }
    __syncthreads();

    for (int t = tid; t < NIP; t += blockDim.x) {
        if (t < NI) {
            g_k2u[t] = g_kg[100 + t];
            g_Wi[t]  = (t == 0) ? g_w[100] : 2.0f * g_w[100 + t];
        } else {
            g_Wi[t] = 0.0f;
        }
    }
    __syncthreads();

    for (int t = tid; t < NJP * NZ; t += blockDim.x) {
        int j = t >> 6, z = t & 63;
        float v = 0.0f;
        if (j < NJ) v = g_w[j] * cosf(g_kg[j] * dz[z]);
        g_CZ[t] = v;
    }
    for (int t = tid; t < NIP * NY; t += blockDim.x) {
        int i = t >> 6, y = t & 63;
        float v = 0.0f;
        if (i < NI) v = g_Wi[i] * cosf(g_k2u[i] * dy[y]);
        g_CY[t] = v;
    }
}

// ---------------------------------------------------------------------------
__global__ void __launch_bounds__(256, 3)
spectral_kernel(const float* __restrict__ k1p,
                const float* __restrict__ pLogL,
                const float* __restrict__ pLogT,
                const float* __restrict__ pLogM,
                float* __restrict__ out) {
    extern __shared__ float smem[];
    float* sPhi = smem;   // NIP * SPHI_LD floats (live during chunk loop)
    float* sG   = smem;   // NIP * SG_LD floats (aliased; live after loop)
    __shared__ float sRed[8];
    __shared__ float sInvDen;

    const int tid = threadIdx.x;
    const int a   = blockIdx.x;

    const float k1     = __ldg(&k1p[a]);
    const float L      = expf(__ldg(pLogL));
    const float T      = expf(__ldg(pLogT));
    const float M      = expf(__ldg(pLogM));
    const float L2     = L * L;
    const float M4pi   = M * 0.079577471545947667884f;
    const float k1sq   = k1 * k1;
    const float inv_k1 = 1.0f / k1;

    const int jl = tid & 31;   // phase A column
    const int i0 = tid >> 5;   // phase A row base
    const int tz = tid & 15;   // phase B z-quad
    const int ti = tid >> 4;   // phase B row group

    u64 acc2[7][2];
#pragma unroll
    for (int r = 0; r < 7; ++r) { acc2[r][0] = 0ull; acc2[r][1] = 0ull; }

    float f1 = 0.0f;

    const char* czBase = (const char*)&g_CZ[4 * tz];

    for (int ch = 0; ch < NCHUNK; ++ch) {
        const int jbase = ch * CHUNK;
        const int j = jbase + jl;
        const bool jvalid = (j < NJ);
        const float k3v = jvalid ? __ldg(&g_kg[j]) : 0.0f;
        const float w3v = jvalid ? __ldg(&g_w[j]) : 0.0f;
        const float k3sq = k3v * k3v;

        // --- Phase A: Phi chunk into smem ---
#pragma unroll 1
        for (int k = 0; k < 14; ++k) {
            const int i = i0 + 8 * k;
            float phi = 0.0f;
            if (i < NI && jvalid) {
                const float k2   = __ldg(&g_k2u[i]);
                const float s    = fmaf(k2, k2, k1sq);
                const float kk   = s + k3sq;
                const float beta = T * fast_ex2(-(1.0f / 3.0f) * fast_lg2(L2 * kk));
                const float bk1  = beta * k1;
                const float k30  = k3v + bk1;
                const float kk0  = s + k30 * k30;
                const float q    = L2 * kk0;
                const float e0   = M4pi * (q * q)
                                   * fast_ex2(-(17.0f / 6.0f) * fast_lg2(1.0f + q));
                const float rsq    = fast_rsq(s);
                const float inv_s  = rsq * rsq;
                const float inv_kk = fast_rcp(kk);
                const float C1 = bk1 * k1
                                 * (kk0 - 2.0f * k30 * k30 + bk1 * k30)
                                 * (inv_kk * inv_s);
                const float yat = bk1 * s * rsq;          // beta*k1*sqrt(s) > 0
                const float xat = kk0 - k30 * bk1;
                const float at  = fast_atan2_pos(yat, xat);
                const float C2  = k2 * kk0 * (inv_s * rsq) * at;
                const float zeta = C1 - k2 * inv_k1 * C2;
                const float ik0  = fast_rcp(kk0);
                phi = e0 * ik0 * ik0
                      * (kk0 - k1sq - 2.0f * k1 * k30 * zeta + s * zeta * zeta);
                f1 = fmaf(phi, __ldg(&g_Wi[i]) * w3v, f1);
            }
            sPhi[i * SPHI_LD + jl] = phi;
        }
        __syncthreads();

        // --- Phase B: G += Phi_chunk * CZ_chunk (f32x2 packed) ---
#pragma unroll 4
        for (int p = 0; p < CHUNK / 2; ++p) {
            const int jl2 = 2 * p;
            const int jg  = jbase + jl2;
            const ulonglong2 cz0 = *(const ulonglong2*)(czBase + (size_t)jg * (NZ * 4));
            const ulonglong2 cz1 = *(const ulonglong2*)(czBase + (size_t)(jg + 1) * (NZ * 4));
#pragma unroll
            for (int r = 0; r < 7; ++r) {
                const float2 ph2 = *(const float2*)&sPhi[(7 * ti + r) * SPHI_LD + jl2];
                const u64 pa = pack2dup(ph2.x);
                const u64 pb = pack2dup(ph2.y);
                ffma2(acc2[r][0], pa, cz0.x);
                ffma2(acc2[r][1], pa, cz0.y);
                ffma2(acc2[r][0], pb, cz1.x);
                ffma2(acc2[r][1], pb, cz1.y);
            }
        }
        __syncthreads();
    }

    // dump G to smem (sG aliases sPhi; all Phi reads done)
#pragma unroll
    for (int r = 0; r < 7; ++r) {
        const int i = 7 * ti + r;
        const float2 lo = unpack2(acc2[r][0]);
        const float2 hi = unpack2(acc2[r][1]);
        float4 v; v.x = lo.x; v.y = lo.y; v.z = hi.x; v.w = hi.y;
        *reinterpret_cast<float4*>(&sG[i * SG_LD + 4 * tz]) = v;
    }

    // reduce F1 -> 1/|F1|
#pragma unroll
    for (int off = 16; off > 0; off >>= 1)
        f1 += __shfl_down_sync(0xffffffffu, f1, off);
    if ((tid & 31) == 0) sRed[tid >> 5] = f1;
    __syncthreads();
    if (tid == 0) {
        float s = 0.0f;
#pragma unroll
        for (int u = 0; u < 8; ++u) s += sRed[u];
        sInvDen = __fdividef(1.0f, fabsf(s));
    }
    __syncthreads();

    // --- Phase C: out[y,z] = (sum_i CY[i,y]*G[i,z]) * invDen (f32x2 packed) ---
    const int tz2 = tid & 15;
    const int ty2 = tid >> 4;
    u64 o2[4][2];
#pragma unroll
    for (int cy = 0; cy < 4; ++cy) { o2[cy][0] = 0ull; o2[cy][1] = 0ull; }

#pragma unroll 4
    for (int i = 0; i < NIP; ++i) {
        const float4 cy = *reinterpret_cast<const float4*>(&g_CY[i * NY + 4 * ty2]);
        const ulonglong2 g2 = *reinterpret_cast<const ulonglong2*>(&sG[i * SG_LD + 4 * tz2]);
        const u64 c0 = pack2dup(cy.x);
        const u64 c1 = pack2dup(cy.y);
        const u64 c2 = pack2dup(cy.z);
        const u64 c3 = pack2dup(cy.w);
        ffma2(o2[0][0], c0, g2.x); ffma2(o2[0][1], c0, g2.y);
        ffma2(o2[1][0], c1, g2.x); ffma2(o2[1][1], c1, g2.y);
        ffma2(o2[2][0], c2, g2.x); ffma2(o2[2][1], c2, g2.y);
        ffma2(o2[3][0], c3, g2.x); ffma2(o2[3][1], c3, g2.y);
    }

    const float inv = sInvDen;
    float* outa = out + (size_t)a * (NY * NZ);
#pragma unroll
    for (int cy = 0; cy < 4; ++cy) {
        const int y = 4 * ty2 + cy;
        const float2 lo = unpack2(o2[cy][0]);
        const float2 hi = unpack2(o2[cy][1]);
        float4 v;
        v.x = lo.x * inv;
        v.y = lo.y * inv;
        v.z = hi.x * inv;
        v.w = hi.y * inv;
        *reinterpret_cast<float4*>(&outa[y * NZ + 4 * tz2]) = v;
    }
}

// ---------------------------------------------------------------------------
extern "C" void kernel_launch(void* const* d_in, const int* in_sizes, int n_in,
                              void* d_out, int out_size) {
    const float* k1 = (const float*)d_in[0];
    const float* dy = (const float*)d_in[1];
    const float* dz = (const float*)d_in[2];
    const float* lL = (const float*)d_in[3];
    const float* lT = (const float*)d_in[4];
    const float* lM = (const float*)d_in[5];

    const int na = in_sizes[0];

    setup_kernel<<<1, 256>>>(dy, dz);

    const size_t smem = (size_t)(NIP * SG_LD) * sizeof(float);  // sPhi aliased inside
    spectral_kernel<<<na, 256, smem>>>(k1, lL, lT, lM, (float*)d_out);
}